// round 11
// baseline (speedup 1.0000x reference)
#include <cuda_runtime.h>
#include <cuda_bf16.h>
#include <cstdint>

#define NUM_CH   544     // 32 batches * 17 keypoints
#define HH       256
#define WW       256
#define MAXP     30
#define STRIDE_  4
#define THRESH   0.1f
#define CUT      0.9985f // ~98 threshold-only candidates/channel expected
#define CAP      512
#define FULL     0xffffffffu

#define T1       256
#define BPC      8                  // scan blocks per channel
#define NBLK     (NUM_CH * BPC)     // 4352 blocks
#define PF4      2048               // float4 per part-channel (16384/8)

// Per-channel state (zero-initialized at module load; the selecting block
// resets both counters at the end of each call -> deterministic for replay).
__device__ int   g_cnt [NUM_CH];
__device__ int   g_done[NUM_CH];
__device__ float g_cs  [NUM_CH * CAP];
__device__ int   g_ci  [NUM_CH * CAP];

// Fallback scratch (exact path, never triggered on this input).
__device__ float g_fb_score[(size_t)NUM_CH * 65536];
__device__ int   g_fb_idx  [(size_t)NUM_CH * 65536];

// ---------------- Fallback: full NMS scan (exact; 8 warps x 32 rows) --------
static __device__ __noinline__ void scan_pass(const float* __restrict__ chm,
                                              float cut, float* ds, int* di,
                                              int cap, int* cnt)
{
    const int lane = threadIdx.x & 31;
    const int wid  = threadIdx.x >> 5;   // 0..7
    const int r0   = wid * 32;
    const int c0   = lane * 8;
    const float NI = __int_as_float(0xff800000);

    float P0[8], P1[8], P2[8], vD[8], rmA[8], rmB[8];

    auto LD = [&](int row, float* dst) {
        if ((unsigned)row < HH) {
            const float4 lo = *(const float4*)(chm + row * WW + c0);
            const float4 hi = *(const float4*)(chm + row * WW + c0 + 4);
            dst[0]=lo.x; dst[1]=lo.y; dst[2]=lo.z; dst[3]=lo.w;
            dst[4]=hi.x; dst[5]=hi.y; dst[6]=hi.z; dst[7]=hi.w;
        } else {
            for (int i = 0; i < 8; ++i) dst[i] = NI;
        }
    };

    LD(r0 - 1, P0);
    LD(r0,     P1);
    for (int i = 0; i < 8; ++i) { rmA[i] = NI; rmB[i] = NI; vD[i] = NI; }

    for (int t = 0; t < 32 + 2; ++t) {
        const int rr = r0 - 1 + t;
        if (t <= 31) {
            LD(rr + 2, P2);
        } else {
            for (int i = 0; i < 8; ++i) P2[i] = NI;
        }
        float lft = __shfl_up_sync(FULL, P0[7], 1);
        if (lane == 0)  lft = NI;
        float rgt = __shfl_down_sync(FULL, P0[0], 1);
        if (lane == 31) rgt = NI;

        float m[7];
        for (int i = 0; i < 7; ++i) m[i] = fmaxf(P0[i], P0[i + 1]);
        float rmC[8];
        rmC[0] = fmaxf(lft, m[0]);
        for (int i = 1; i < 7; ++i) rmC[i] = fmaxf(m[i - 1], P0[i + 1]);
        rmC[7] = fmaxf(m[6], rgt);

        if (t >= 2) {
            const int dr = rr - 1;
            for (int i = 0; i < 8; ++i) {
                const float w = fmaxf(fmaxf(rmA[i], rmB[i]), rmC[i]);
                if (vD[i] > cut && vD[i] == w) {
                    const int p = atomicAdd(cnt, 1);
                    if (p < cap) { ds[p] = vD[i]; di[p] = dr * WW + c0 + i; }
                }
            }
        }
        for (int i = 0; i < 8; ++i) {
            rmA[i] = rmB[i]; rmB[i] = rmC[i];
            vD[i]  = P0[i];  P0[i]  = P1[i]; P1[i] = P2[i];
        }
    }
}

// ---------------- Fused kernel: scan part-channel + last-arriver selection --
struct Sm {
    float ps[CAP]; int pi[CAP];
    int pcount;
    int fcount;
    int sel;
};

__global__ __launch_bounds__(T1, 6)
void pose_post_kernel(const float* __restrict__ hm, float* __restrict__ out)
{
    __shared__ Sm s;
    const int tid = threadIdx.x;
    const int ch  = blockIdx.x >> 3;
    const int pr  = blockIdx.x & 7;
    const float NI = __int_as_float(0xff800000);

    // ---- Phase A: stream this part-channel (8 coalesced float4/thread) -----
    // Two front-batched groups of 4 independent LDG.128 (16 data registers),
    // keeping the hot path within the 42-reg cap for 6 CTAs/SM.
    const float4* __restrict__ hm4 = (const float4*)hm;
    const int q0 = ch * 16384 + pr * PF4;
    float* __restrict__ cs = g_cs + ch * CAP;
    int*   __restrict__ ci = g_ci + ch * CAP;

    #pragma unroll
    for (int g = 0; g < 2; ++g) {
        float4 v[4];
        #pragma unroll
        for (int i = 0; i < 4; ++i)
            v[i] = hm4[q0 + (g * 4 + i) * T1 + tid];

        #pragma unroll
        for (int i = 0; i < 4; ++i) {
            const float mx = fmaxf(fmaxf(v[i].x, v[i].y), fmaxf(v[i].z, v[i].w));
            if (mx > CUT) {                     // ~0.6% of float4s
                const int fb = ((q0 + (g * 4 + i) * T1 + tid) & 16383) * 4;
                if (v[i].x > CUT) { int p = atomicAdd(&g_cnt[ch], 1); if (p < CAP) { cs[p] = v[i].x; ci[p] = fb;     } }
                if (v[i].y > CUT) { int p = atomicAdd(&g_cnt[ch], 1); if (p < CAP) { cs[p] = v[i].y; ci[p] = fb + 1; } }
                if (v[i].z > CUT) { int p = atomicAdd(&g_cnt[ch], 1); if (p < CAP) { cs[p] = v[i].z; ci[p] = fb + 2; } }
                if (v[i].w > CUT) { int p = atomicAdd(&g_cnt[ch], 1); if (p < CAP) { cs[p] = v[i].w; ci[p] = fb + 3; } }
            }
        }
    }

    // ---- Release: every thread fences its appends, block-sync, one arrive --
    __threadfence();
    __syncthreads();
    if (tid == 0) {
        const int old = atomicAdd(&g_done[ch], 1);
        s.sel = (old == BPC - 1);
        s.pcount = 0; s.fcount = 0;
    }
    __syncthreads();
    if (!s.sel) return;
    __threadfence();                             // acquire others' appends

    const float* __restrict__ chm = hm + (size_t)ch * HH * WW;
    const int cnt = g_cnt[ch];
    const bool ok = (cnt <= CAP);
    const int nc  = min(cnt, CAP);

    // ---- Phase B: 3x3 window check (channel is L2-hot: just streamed) ------
    if (ok) {
        for (int i = tid; i < nc; i += T1) {
            const float v  = cs[i];
            const int   id = ci[i];
            const int x = id & (WW - 1);
            const int y = id >> 8;
            const float* rp = chm + id;
            bool peak = true;
            if (x > 0      && __ldg(rp - 1)        > v) peak = false;
            if (x < WW - 1 && __ldg(rp + 1)        > v) peak = false;
            if (y > 0) {
                if (              __ldg(rp - WW)     > v) peak = false;
                if (x > 0      && __ldg(rp - WW - 1) > v) peak = false;
                if (x < WW - 1 && __ldg(rp - WW + 1) > v) peak = false;
            }
            if (y < HH - 1) {
                if (              __ldg(rp + WW)     > v) peak = false;
                if (x > 0      && __ldg(rp + WW - 1) > v) peak = false;
                if (x < WW - 1 && __ldg(rp + WW + 1) > v) peak = false;
            }
            if (peak) {
                const int p = atomicAdd(&s.pcount, 1);   // p < nc <= CAP
                s.ps[p] = v; s.pi[p] = id;
            }
        }
    }
    __syncthreads();

    int n = ok ? s.pcount : 0;
    const float* rs = s.ps;
    const int*   ri = s.pi;

    if (!ok || n < MAXP) {
        // Exact fallback: full NMS at THRESH into global scratch.
        float* gs = g_fb_score + (size_t)ch * 65536;
        int*   gi = g_fb_idx   + (size_t)ch * 65536;
        scan_pass(chm, THRESH, gs, gi, 65536, &s.fcount);
        __syncthreads();
        n = min(s.fcount, 65536);
        rs = gs; ri = gi;
    }

    // ---- Exact rank (score desc, idx asc tiebreak == lax.top_k order) ------
    for (int i = tid; i < n; i += T1) {
        const float sc = rs[i];
        const int   id = ri[i];
        int rank = 0;
        for (int j = 0; j < n; ++j) {
            const float sj = rs[j];
            rank += (sj > sc) || (sj == sc && ri[j] < id);
        }
        if (rank < MAXP) {
            const int x  = id & (WW - 1);
            const int y  = id >> 8;
            const int ob = ch * MAXP + rank;
            out[ob * 2]                 = (float)(x * STRIDE_);
            out[ob * 2 + 1]             = (float)(y * STRIDE_);
            out[NUM_CH * MAXP * 2 + ob] = sc;     // scores segment
            out[NUM_CH * MAXP * 3 + ob] = 1.0f;   // valid segment
        }
    }
    // Padding (never needed on this input; keeps d_out fully written).
    for (int r = n + tid; r < MAXP; r += T1) {
        const int ob = ch * MAXP + r;
        out[ob * 2]                 = 0.0f;
        out[ob * 2 + 1]             = 0.0f;
        out[NUM_CH * MAXP * 2 + ob] = NI;
        out[NUM_CH * MAXP * 3 + ob] = 0.0f;
    }

    // Reset per-channel state for the next call / graph replay.
    __syncthreads();
    if (tid == 0) { g_cnt[ch] = 0; g_done[ch] = 0; }
}

extern "C" void kernel_launch(void* const* d_in, const int* in_sizes, int n_in,
                              void* d_out, int out_size)
{
    const float* hm = (const float*)d_in[0];
    float* out = (float*)d_out;
    pose_post_kernel<<<NBLK, T1>>>(hm, out);
}

// round 12
// speedup vs baseline: 1.0363x; 1.0363x over previous
#include <cuda_runtime.h>
#include <cuda_bf16.h>
#include <cstdint>

#define NUM_CH   544     // 32 batches * 17 keypoints
#define HH       256
#define WW       256
#define MAXP     30
#define STRIDE_  4
#define THRESH   0.1f
#define CUT      0.9985f // ~98 threshold-only candidates/channel expected
#define CAP      512
#define FULL     0xffffffffu

#define T1       256
#define BPC      4                  // scan blocks per channel (64KB part each)
#define NBLK     (NUM_CH * BPC)     // 2176 blocks
#define STAGE_B  8192               // bytes per pipeline stage
#define STAGE_F4 512                // float4 per stage
#define NSLOT    4                  // smem ring slots
#define NSTAGE   8                  // stages per block (8 * 8KB = 64KB)

// Per-channel state (zero-initialized at load; selecting block resets at end
// of every call -> deterministic across graph replays).
__device__ int   g_cnt [NUM_CH];
__device__ int   g_done[NUM_CH];
__device__ float g_cs  [NUM_CH * CAP];
__device__ int   g_ci  [NUM_CH * CAP];

// Fallback scratch (exact path, never triggered on this input).
__device__ float g_fb_score[(size_t)NUM_CH * 65536];
__device__ int   g_fb_idx  [(size_t)NUM_CH * 65536];

// ---------------- tiny PTX helpers (mbarrier + bulk async copy) -------------
static __device__ __forceinline__ uint32_t smem_u32(const void* p) {
    return (uint32_t)__cvta_generic_to_shared(p);
}
static __device__ __forceinline__ void mbar_init(uint32_t a, uint32_t cnt) {
    asm volatile("mbarrier.init.shared.b64 [%0], %1;" :: "r"(a), "r"(cnt) : "memory");
}
static __device__ __forceinline__ void fence_proxy_async_cta() {
    asm volatile("fence.proxy.async.shared::cta;" ::: "memory");
}
static __device__ __forceinline__ void mbar_expect_tx(uint32_t a, uint32_t bytes) {
    asm volatile("mbarrier.arrive.expect_tx.shared.b64 _, [%0], %1;"
                 :: "r"(a), "r"(bytes) : "memory");
}
static __device__ __forceinline__ void bulk_g2s(uint32_t dst, const void* src,
                                                uint32_t bytes, uint32_t mbar) {
    asm volatile(
        "cp.async.bulk.shared::cluster.global.mbarrier::complete_tx::bytes "
        "[%0], [%1], %2, [%3];"
        :: "r"(dst), "l"(src), "r"(bytes), "r"(mbar) : "memory");
}
static __device__ __forceinline__ void mbar_wait(uint32_t a, uint32_t parity) {
    asm volatile(
        "{\n\t.reg .pred P;\n\t"
        "WL_%=:\n\t"
        "mbarrier.try_wait.parity.acquire.cta.shared::cta.b64 P, [%0], %1, 0x989680;\n\t"
        "@P bra WD_%=;\n\t"
        "bra WL_%=;\n\t"
        "WD_%=:\n\t}"
        :: "r"(a), "r"(parity) : "memory");
}

// ---------------- Fallback: full NMS scan (exact; 8 warps x 32 rows) --------
static __device__ __noinline__ void scan_pass(const float* __restrict__ chm,
                                              float cut, float* ds, int* di,
                                              int cap, int* cnt)
{
    const int lane = threadIdx.x & 31;
    const int wid  = threadIdx.x >> 5;   // 0..7
    const int r0   = wid * 32;
    const int c0   = lane * 8;
    const float NI = __int_as_float(0xff800000);

    float P0[8], P1[8], P2[8], vD[8], rmA[8], rmB[8];

    auto LD = [&](int row, float* dst) {
        if ((unsigned)row < HH) {
            const float4 lo = *(const float4*)(chm + row * WW + c0);
            const float4 hi = *(const float4*)(chm + row * WW + c0 + 4);
            dst[0]=lo.x; dst[1]=lo.y; dst[2]=lo.z; dst[3]=lo.w;
            dst[4]=hi.x; dst[5]=hi.y; dst[6]=hi.z; dst[7]=hi.w;
        } else {
            for (int i = 0; i < 8; ++i) dst[i] = NI;
        }
    };

    LD(r0 - 1, P0);
    LD(r0,     P1);
    for (int i = 0; i < 8; ++i) { rmA[i] = NI; rmB[i] = NI; vD[i] = NI; }

    for (int t = 0; t < 32 + 2; ++t) {
        const int rr = r0 - 1 + t;
        if (t <= 31) {
            LD(rr + 2, P2);
        } else {
            for (int i = 0; i < 8; ++i) P2[i] = NI;
        }
        float lft = __shfl_up_sync(FULL, P0[7], 1);
        if (lane == 0)  lft = NI;
        float rgt = __shfl_down_sync(FULL, P0[0], 1);
        if (lane == 31) rgt = NI;

        float m[7];
        for (int i = 0; i < 7; ++i) m[i] = fmaxf(P0[i], P0[i + 1]);
        float rmC[8];
        rmC[0] = fmaxf(lft, m[0]);
        for (int i = 1; i < 7; ++i) rmC[i] = fmaxf(m[i - 1], P0[i + 1]);
        rmC[7] = fmaxf(m[6], rgt);

        if (t >= 2) {
            const int dr = rr - 1;
            for (int i = 0; i < 8; ++i) {
                const float w = fmaxf(fmaxf(rmA[i], rmB[i]), rmC[i]);
                if (vD[i] > cut && vD[i] == w) {
                    const int p = atomicAdd(cnt, 1);
                    if (p < cap) { ds[p] = vD[i]; di[p] = dr * WW + c0 + i; }
                }
            }
        }
        for (int i = 0; i < 8; ++i) {
            rmA[i] = rmB[i]; rmB[i] = rmC[i];
            vD[i]  = P0[i];  P0[i]  = P1[i]; P1[i] = P2[i];
        }
    }
}

// ---------------- Fused kernel: TMA-staged scan + last-arriver selection ----
struct Sm {
    float4 buf[NSLOT * STAGE_F4];          // 32 KB ring
    unsigned long long mbar[NSLOT];
    float ps[CAP]; int pi[CAP];            // verified peaks
    int pcount;
    int fcount;
    int sel;
};

__global__ __launch_bounds__(T1, 6)
void pose_post_kernel(const float* __restrict__ hm, float* __restrict__ out)
{
    __shared__ Sm s;
    const int tid = threadIdx.x;
    const int ch  = blockIdx.x >> 2;
    const int pr  = blockIdx.x & 3;
    const float NI = __int_as_float(0xff800000);

    const float* __restrict__ part = hm + (size_t)ch * 65536 + pr * 16384;
    float* __restrict__ cs = g_cs + ch * CAP;
    int*   __restrict__ ci = g_ci + ch * CAP;

    // ---- init mbarriers (count=1: tid0's expect_tx is the sole arrival) ----
    if (tid == 0) {
        #pragma unroll
        for (int i = 0; i < NSLOT; ++i)
            mbar_init(smem_u32(&s.mbar[i]), 1);
        fence_proxy_async_cta();
        s.pcount = 0; s.fcount = 0;
    }
    __syncthreads();

    // ---- prologue: issue stages 0..2 -----------------------------------
    if (tid == 0) {
        #pragma unroll
        for (int k = 0; k < 3; ++k) {
            const uint32_t mb = smem_u32(&s.mbar[k]);
            mbar_expect_tx(mb, STAGE_B);
            bulk_g2s(smem_u32(&s.buf[k * STAGE_F4]), part + k * 2048, STAGE_B, mb);
        }
    }

    // ---- pipeline: wait / scan-from-smem / sync / issue st+3 ---------------
    for (int st = 0; st < NSTAGE; ++st) {
        mbar_wait(smem_u32(&s.mbar[st & 3]), (st >> 2) & 1);

        const float4* sp = s.buf + (st & 3) * STAGE_F4;
        #pragma unroll
        for (int k = 0; k < 2; ++k) {
            const float4 v = sp[tid + k * T1];
            const float mx = fmaxf(fmaxf(v.x, v.y), fmaxf(v.z, v.w));
            if (mx > CUT) {                       // ~0.6% of float4s
                const int fb = pr * 16384 + st * 2048 + (tid + k * T1) * 4;
                if (v.x > CUT) { int p = atomicAdd(&g_cnt[ch], 1); if (p < CAP) { cs[p] = v.x; ci[p] = fb;     } }
                if (v.y > CUT) { int p = atomicAdd(&g_cnt[ch], 1); if (p < CAP) { cs[p] = v.y; ci[p] = fb + 1; } }
                if (v.z > CUT) { int p = atomicAdd(&g_cnt[ch], 1); if (p < CAP) { cs[p] = v.z; ci[p] = fb + 2; } }
                if (v.w > CUT) { int p = atomicAdd(&g_cnt[ch], 1); if (p < CAP) { cs[p] = v.w; ci[p] = fb + 3; } }
            }
        }
        __syncthreads();   // all lanes done reading slot (st-1)&3 and st&3
        if (tid == 0 && st + 3 < NSTAGE) {
            const int k = st + 3;
            const uint32_t mb = smem_u32(&s.mbar[k & 3]);
            mbar_expect_tx(mb, STAGE_B);
            bulk_g2s(smem_u32(&s.buf[(k & 3) * STAGE_F4]), part + k * 2048, STAGE_B, mb);
        }
    }

    // ---- Release: fence appends, block-sync, one arrival atomic ------------
    __threadfence();
    __syncthreads();
    if (tid == 0) {
        const int old = atomicAdd(&g_done[ch], 1);
        s.sel = (old == BPC - 1);
    }
    __syncthreads();
    if (!s.sel) return;
    __threadfence();                             // acquire others' appends

    const float* __restrict__ chm = hm + (size_t)ch * HH * WW;
    const int cnt = g_cnt[ch];
    const bool ok = (cnt <= CAP);
    const int nc  = min(cnt, CAP);

    // ---- Phase B: 3x3 window check (channel is L2-hot from the TMA fills) --
    if (ok) {
        for (int i = tid; i < nc; i += T1) {
            const float v  = cs[i];
            const int   id = ci[i];
            const int x = id & (WW - 1);
            const int y = id >> 8;
            const float* rp = chm + id;
            bool peak = true;
            if (x > 0      && __ldg(rp - 1)        > v) peak = false;
            if (x < WW - 1 && __ldg(rp + 1)        > v) peak = false;
            if (y > 0) {
                if (              __ldg(rp - WW)     > v) peak = false;
                if (x > 0      && __ldg(rp - WW - 1) > v) peak = false;
                if (x < WW - 1 && __ldg(rp - WW + 1) > v) peak = false;
            }
            if (y < HH - 1) {
                if (              __ldg(rp + WW)     > v) peak = false;
                if (x > 0      && __ldg(rp + WW - 1) > v) peak = false;
                if (x < WW - 1 && __ldg(rp + WW + 1) > v) peak = false;
            }
            if (peak) {
                const int p = atomicAdd(&s.pcount, 1);   // p < nc <= CAP
                s.ps[p] = v; s.pi[p] = id;
            }
        }
    }
    __syncthreads();

    int n = ok ? s.pcount : 0;
    const float* rs = s.ps;
    const int*   ri = s.pi;

    if (!ok || n < MAXP) {
        // Exact fallback: full NMS at THRESH into global scratch.
        float* gs = g_fb_score + (size_t)ch * 65536;
        int*   gi = g_fb_idx   + (size_t)ch * 65536;
        scan_pass(chm, THRESH, gs, gi, 65536, &s.fcount);
        __syncthreads();
        n = min(s.fcount, 65536);
        rs = gs; ri = gi;
    }

    // ---- Exact rank (score desc, idx asc tiebreak == lax.top_k order) ------
    for (int i = tid; i < n; i += T1) {
        const float sc = rs[i];
        const int   id = ri[i];
        int rank = 0;
        for (int j = 0; j < n; ++j) {
            const float sj = rs[j];
            rank += (sj > sc) || (sj == sc && ri[j] < id);
        }
        if (rank < MAXP) {
            const int x  = id & (WW - 1);
            const int y  = id >> 8;
            const int ob = ch * MAXP + rank;
            out[ob * 2]                 = (float)(x * STRIDE_);
            out[ob * 2 + 1]             = (float)(y * STRIDE_);
            out[NUM_CH * MAXP * 2 + ob] = sc;     // scores segment
            out[NUM_CH * MAXP * 3 + ob] = 1.0f;   // valid segment
        }
    }
    // Padding (never needed on this input; keeps d_out fully written).
    for (int r = n + tid; r < MAXP; r += T1) {
        const int ob = ch * MAXP + r;
        out[ob * 2]                 = 0.0f;
        out[ob * 2 + 1]             = 0.0f;
        out[NUM_CH * MAXP * 2 + ob] = NI;
        out[NUM_CH * MAXP * 3 + ob] = 0.0f;
    }

    // Reset per-channel state for the next call / graph replay.
    __syncthreads();
    if (tid == 0) { g_cnt[ch] = 0; g_done[ch] = 0; }
}

extern "C" void kernel_launch(void* const* d_in, const int* in_sizes, int n_in,
                              void* d_out, int out_size)
{
    const float* hm = (const float*)d_in[0];
    float* out = (float*)d_out;
    pose_post_kernel<<<NBLK, T1>>>(hm, out);
}

// round 15
// speedup vs baseline: 1.3202x; 1.2740x over previous
#include <cuda_runtime.h>
#include <cuda_bf16.h>
#include <cstdint>

#define NUM_CH   544     // 32 batches * 17 keypoints
#define HH       256
#define WW       256
#define MAXP     30
#define STRIDE_  4
#define THRESH   0.1f
#define CUT      0.9985f // ~98 threshold-only candidates/channel expected
#define CAP      512
#define THREADS  512
#define RPW      16
#define FULL     0xffffffffu

// Fallback scratch (exact path, never triggered on this input).
__device__ float g_fb_score[(size_t)NUM_CH * 65536];
__device__ int   g_fb_idx  [(size_t)NUM_CH * 65536];

struct Sm {
    float cs[CAP]; int ci[CAP];   // threshold-only candidates
    float ps[CAP]; int pi[CAP];   // verified peaks
    int ccount;
    int pcount;
};

// Fallback: full NMS scan with register pipeline (proven). Keep pixel iff
// v > cut AND v == max of full 3x3 window. Never runs on this input.
static __device__ __noinline__ void scan_pass(const float* __restrict__ chm,
                                              float cut, float* ds, int* di,
                                              int cap, int* cnt)
{
    const int lane = threadIdx.x & 31;
    const int wid  = threadIdx.x >> 5;
    const int r0   = wid * RPW;
    const int c0   = lane * 8;
    const float NI = __int_as_float(0xff800000);

    float P0[8], P1[8], P2[8], vD[8], rmA[8], rmB[8];

    auto LD = [&](int row, float* dst) {
        if ((unsigned)row < HH) {
            const float4 lo = *(const float4*)(chm + row * WW + c0);
            const float4 hi = *(const float4*)(chm + row * WW + c0 + 4);
            dst[0]=lo.x; dst[1]=lo.y; dst[2]=lo.z; dst[3]=lo.w;
            dst[4]=hi.x; dst[5]=hi.y; dst[6]=hi.z; dst[7]=hi.w;
        } else {
            for (int i = 0; i < 8; ++i) dst[i] = NI;
        }
    };

    LD(r0 - 1, P0);
    LD(r0,     P1);
    for (int i = 0; i < 8; ++i) { rmA[i] = NI; rmB[i] = NI; vD[i] = NI; }

    for (int t = 0; t < RPW + 2; ++t) {
        const int rr = r0 - 1 + t;
        if (t <= RPW - 1) {
            LD(rr + 2, P2);
        } else {
            for (int i = 0; i < 8; ++i) P2[i] = NI;
        }
        float lft = __shfl_up_sync(FULL, P0[7], 1);
        if (lane == 0)  lft = NI;
        float rgt = __shfl_down_sync(FULL, P0[0], 1);
        if (lane == 31) rgt = NI;

        float m[7];
        for (int i = 0; i < 7; ++i) m[i] = fmaxf(P0[i], P0[i + 1]);
        float rmC[8];
        rmC[0] = fmaxf(lft, m[0]);
        for (int i = 1; i < 7; ++i) rmC[i] = fmaxf(m[i - 1], P0[i + 1]);
        rmC[7] = fmaxf(m[6], rgt);

        if (t >= 2) {
            const int dr = rr - 1;
            for (int i = 0; i < 8; ++i) {
                const float w = fmaxf(fmaxf(rmA[i], rmB[i]), rmC[i]);
                if (vD[i] > cut && vD[i] == w) {
                    const int p = atomicAdd(cnt, 1);
                    if (p < cap) { ds[p] = vD[i]; di[p] = dr * WW + c0 + i; }
                }
            }
        }
        for (int i = 0; i < 8; ++i) {
            rmA[i] = rmB[i]; rmB[i] = rmC[i];
            vD[i]  = P0[i];  P0[i]  = P1[i]; P1[i] = P2[i];
        }
    }
}

__global__ __launch_bounds__(THREADS, 4)
void pose_post_kernel(const float* __restrict__ hm, float* __restrict__ out)
{
    __shared__ Sm s;
    const int tid = threadIdx.x;
    const int ch  = blockIdx.x;
    const float* __restrict__ chm = hm + (size_t)ch * HH * WW;
    const float NI = __int_as_float(0xff800000);

    if (tid == 0) { s.ccount = 0; s.pcount = 0; }
    __syncthreads();

    // ---- Phase A: streaming threshold scan with PHASE-ROTATED chunk order --
    // Each (block, warp) iterates the 32 chunk-steps in a rotated order so the
    // chip-wide instantaneous address set spreads across all LTS hash classes
    // instead of every block hitting the same 2KB-phase simultaneously.
    const float4* __restrict__ chm4 = (const float4*)chm;
    const int wph = ((blockIdx.x * 7) + (tid >> 5) * 5) & 31;

    #pragma unroll 4
    for (int i = 0; i < 32; ++i) {
        const int j = (i + wph) & 31;           // permutation of 0..31
        const int q = j * THREADS + tid;
        const float4 v = chm4[q];
        const float mx = fmaxf(fmaxf(v.x, v.y), fmaxf(v.z, v.w));
        if (mx > CUT) {                         // ~0.6% of float4s
            const int fb = q * 4;
            if (v.x > CUT) { int p = atomicAdd(&s.ccount, 1); if (p < CAP) { s.cs[p] = v.x; s.ci[p] = fb;     } }
            if (v.y > CUT) { int p = atomicAdd(&s.ccount, 1); if (p < CAP) { s.cs[p] = v.y; s.ci[p] = fb + 1; } }
            if (v.z > CUT) { int p = atomicAdd(&s.ccount, 1); if (p < CAP) { s.cs[p] = v.z; s.ci[p] = fb + 2; } }
            if (v.w > CUT) { int p = atomicAdd(&s.ccount, 1); if (p < CAP) { s.cs[p] = v.w; s.ci[p] = fb + 3; } }
        }
    }
    __syncthreads();

    const int nc = s.ccount;
    const bool ok = (nc <= CAP);

    // ---- Phase B: 3x3 window check on the ~98 candidates (L2-hot reads) ----
    if (ok) {
        for (int i = tid; i < nc; i += THREADS) {
            const float v  = s.cs[i];
            const int   id = s.ci[i];
            const int x = id & (WW - 1);
            const int y = id >> 8;
            const float* rp = chm + id;
            bool peak = true;
            if (x > 0      && __ldg(rp - 1)        > v) peak = false;
            if (x < WW - 1 && __ldg(rp + 1)        > v) peak = false;
            if (y > 0) {
                if (              __ldg(rp - WW)     > v) peak = false;
                if (x > 0      && __ldg(rp - WW - 1) > v) peak = false;
                if (x < WW - 1 && __ldg(rp - WW + 1) > v) peak = false;
            }
            if (y < HH - 1) {
                if (              __ldg(rp + WW)     > v) peak = false;
                if (x > 0      && __ldg(rp + WW - 1) > v) peak = false;
                if (x < WW - 1 && __ldg(rp + WW + 1) > v) peak = false;
            }
            if (peak) {
                const int p = atomicAdd(&s.pcount, 1);   // p < nc <= CAP
                s.ps[p] = v; s.pi[p] = id;
            }
        }
        __syncthreads();
    }

    int n = ok ? s.pcount : 0;
    const float* rs = s.ps;
    const int*   ri = s.pi;

    if (!ok || n < MAXP) {
        // Exact fallback: full NMS scan at THRESH into global scratch.
        __syncthreads();
        if (tid == 0) s.ccount = 0;
        __syncthreads();
        float* gs = g_fb_score + (size_t)ch * 65536;
        int*   gi = g_fb_idx   + (size_t)ch * 65536;
        scan_pass(chm, THRESH, gs, gi, 65536, &s.ccount);
        __syncthreads();
        n = min(s.ccount, 65536);
        rs = gs; ri = gi;
    }

    // ---- Exact rank (score desc, idx asc tiebreak == lax.top_k order) ------
    for (int i = tid; i < n; i += THREADS) {
        const float sc = rs[i];
        const int   id = ri[i];
        int rank = 0;
        for (int j = 0; j < n; ++j) {
            const float sj = rs[j];
            rank += (sj > sc) || (sj == sc && ri[j] < id);
        }
        if (rank < MAXP) {
            const int x  = id & (WW - 1);
            const int y  = id >> 8;
            const int ob = ch * MAXP + rank;
            out[ob * 2]                 = (float)(x * STRIDE_);
            out[ob * 2 + 1]             = (float)(y * STRIDE_);
            out[NUM_CH * MAXP * 2 + ob] = sc;     // scores segment
            out[NUM_CH * MAXP * 3 + ob] = 1.0f;   // valid segment
        }
    }
    // Padding (never needed on this input; keeps d_out fully written).
    for (int r = n + tid; r < MAXP; r += THREADS) {
        const int ob = ch * MAXP + r;
        out[ob * 2]                 = 0.0f;
        out[ob * 2 + 1]             = 0.0f;
        out[NUM_CH * MAXP * 2 + ob] = NI;
        out[NUM_CH * MAXP * 3 + ob] = 0.0f;
    }
}

extern "C" void kernel_launch(void* const* d_in, const int* in_sizes, int n_in,
                              void* d_out, int out_size)
{
    const float* hm = (const float*)d_in[0];
    float* out = (float*)d_out;
    pose_post_kernel<<<NUM_CH, THREADS>>>(hm, out);
}